// round 14
// baseline (speedup 1.0000x reference)
#include <cuda_runtime.h>

#define NQ 13
#define FULL 0xffffffffu

// One transfer step (verified R5-R13): v_new = L(v) given wire params.
__device__ __forceinline__ void tstep(
    float i00, float i11, float i01x, float i01y,
    float g0x, float g0y, float g1x, float g1y,
    float gm, float gux, float guy,
    float& o00, float& o11, float& o01x, float& o01y)
{
    const float h00x = fmaf(g0x, i00, fmaf(g1x, i01x, -g1y * i01y));
    const float h00y = fmaf(g0y, i00, fmaf(g1x, i01y,  g1y * i01x));
    const float h01x = fmaf(g1x, i00, fmaf(g0x, i01x, -g0y * i01y));
    const float h01y = fmaf(g1y, i00, fmaf(g0x, i01y,  g0y * i01x));
    const float h10x = fmaf(g1x, i11, fmaf(g0x, i01x,  g0y * i01y));
    const float h10y = fmaf(g1y, i11, fmaf(g0y, i01x, -g0x * i01y));
    const float h11x = fmaf(g0x, i11, fmaf(g1x, i01x,  g1y * i01y));
    const float h11y = fmaf(g0y, i11, fmaf(g1y, i01x, -g1x * i01y));
    const float w00  = fmaf(g0x, h00x, g0y * h00y) + fmaf(g1x, h10x, g1y * h10y);
    const float w01x = fmaf(g0x, h01x, g0y * h01y) + fmaf(g1x, h11x, g1y * h11y);
    const float w01y = fmaf(g0x, h01y, -g0y * h01x) + fmaf(g1x, h11y, -g1y * h11x);
    const float w11  = fmaf(g1x, h01x, g1y * h01y) + fmaf(g0x, h11x, g0y * h11y);
    o00  =  gm * w00;
    o11  = -gm * w11;
    o01x = fmaf(gux, w01x, -guy * w01y);
    o01y = fmaf(gux, w01y,  guy * w01x);
}

// Transfer-matrix contraction with LOG-DEPTH prefix scan.
// One warp per element, 8 warps/CTA (R8/R13 best grid config).
//   - lane l (l<13) computes ALL wire-l params (5 independent sincosf)
//   - lane l builds its 4x4 transfer matrix L_l by applying the step body
//     to the 4 basis vectors (compiler folds constants)
//   - Kogge-Stone scan (4 steps) -> lane l holds P_l = L_l ... L_1
//   - ev[l] = (1,1,2*kappa_{l+1},0) . (P_l . v0), v0 from wire-0 params.
__global__ __launch_bounds__(256, 1)
void qsim_tn(const float* __restrict__ x,
             const float* __restrict__ wts,
             float* __restrict__ out,
             int n)
{
    const int e = blockIdx.x * 8 + (threadIdx.x >> 5);
    const int l = threadIdx.x & 31;
    if (e >= n) return;

    // ---- per-lane params for wire l ----
    float p0x = 1.f, p0y = 0.f, p1x = 0.f, p1y = 0.f;
    float m = 1.f, mux = 0.f, muy = 0.f, kap = 0.f;

    if (l < NQ) {
        const float xv = __ldg(&x[e * NQ + l]);
        const float wa0 = __ldg(&wts[l * 3 + 0]);
        const float wa1 = __ldg(&wts[l * 3 + 1]);
        const float wa2 = __ldg(&wts[l * 3 + 2]);
        const float wb0 = __ldg(&wts[(NQ + l) * 3 + 0]);
        const float wb1 = __ldg(&wts[(NQ + l) * 3 + 1]);
        float s1, c1, s2, c2, sp, cp, sa, ca, sb, cb;
        __sincosf(0.5f * xv * wa0, &s1, &c1);   // RX half
        __sincosf(0.5f * xv * wa1, &s2, &c2);   // RY half
        __sincosf(0.5f * wa2,      &sp, &cp);   // RZ half
        __sincosf(xv * wb0, &sa, &ca);          // layer-2 full angles
        __sincosf(xv * wb1, &sb, &cb);
        const float A = c2 * c1, B = s2 * s1, C = s2 * c1, D = c2 * s1;
        p0x = fmaf(cp, A,  sp * B);
        p0y = fmaf(cp, B, -sp * A);
        p1x = fmaf(cp, C,  sp * D);
        p1y = fmaf(sp, C, -cp * D);
        m   = ca * cb;
        mux = -sb;
        muy = -sa * cb;
        kap = 2.f * fmaf(p0x, p1x, p0y * p1y);
    }

    // ---- build 4x4 transfer matrix L (P[r*4+c]); lane 0 & lanes>=13: I ----
    float P[16];
    if (l >= 1 && l < NQ) {
        tstep(1.f, 0.f, 0.f, 0.f, p0x, p0y, p1x, p1y, m, mux, muy,
              P[0], P[4], P[8],  P[12]);
        tstep(0.f, 1.f, 0.f, 0.f, p0x, p0y, p1x, p1y, m, mux, muy,
              P[1], P[5], P[9],  P[13]);
        tstep(0.f, 0.f, 1.f, 0.f, p0x, p0y, p1x, p1y, m, mux, muy,
              P[2], P[6], P[10], P[14]);
        tstep(0.f, 0.f, 0.f, 1.f, p0x, p0y, p1x, p1y, m, mux, muy,
              P[3], P[7], P[11], P[15]);
    } else {
        #pragma unroll
        for (int i = 0; i < 16; i++) P[i] = 0.f;
        P[0] = P[5] = P[10] = P[15] = 1.f;
    }

    // ---- Kogge-Stone inclusive scan: P_l <- P_l x P_{l-d} ----
    #pragma unroll
    for (int d = 1; d < 16; d <<= 1) {
        float O[16];
        #pragma unroll
        for (int i = 0; i < 16; i++) O[i] = __shfl_up_sync(FULL, P[i], d);
        if (l >= d) {
            float T[16];
            #pragma unroll
            for (int r = 0; r < 4; r++)
                #pragma unroll
                for (int c = 0; c < 4; c++)
                    T[r * 4 + c] = fmaf(P[r * 4 + 0], O[0 * 4 + c],
                                   fmaf(P[r * 4 + 1], O[1 * 4 + c],
                                   fmaf(P[r * 4 + 2], O[2 * 4 + c],
                                        P[r * 4 + 3] * O[3 * 4 + c])));
            #pragma unroll
            for (int i = 0; i < 16; i++) P[i] = T[i];
        }
    }

    // ---- v0 from wire-0 params (broadcast from lane 0) ----
    const float q0x = __shfl_sync(FULL, p0x, 0);
    const float q0y = __shfl_sync(FULL, p0y, 0);
    const float q1x = __shfl_sync(FULL, p1x, 0);
    const float q1y = __shfl_sync(FULL, p1y, 0);
    const float qm  = __shfl_sync(FULL, m,   0);
    const float qux = __shfl_sync(FULL, mux, 0);
    const float quy = __shfl_sync(FULL, muy, 0);
    const float v000  =  qm * fmaf(q0x, q0x, q0y * q0y);
    const float v011  = -qm * fmaf(q1x, q1x, q1y * q1y);
    const float tx    = fmaf(q0x, q1x,  q0y * q1y);
    const float ty    = fmaf(q0x, q1y, -q0y * q1x);
    const float v001x = fmaf(qux, tx, -quy * ty);
    const float v001y = fmaf(qux, ty,  quy * tx);

    // ---- v_l = P_l . v0 ----
    const float r00  = fmaf(P[0],  v000, fmaf(P[1],  v011, fmaf(P[2],  v001x, P[3]  * v001y)));
    const float r11  = fmaf(P[4],  v000, fmaf(P[5],  v011, fmaf(P[6],  v001x, P[7]  * v001y)));
    const float r01x = fmaf(P[8],  v000, fmaf(P[9],  v011, fmaf(P[10], v001x, P[11] * v001y)));

    // ---- ev[l] = v00+v11 + kappa_{l+1} * 2*v01x  (lane 12: kappa=1) ----
    const float knext = __shfl_sync(FULL, kap, (l + 1) & 31);
    const float gk = (l == NQ - 1) ? 1.f : knext;
    const float ev = r00 + r11 + gk * (2.f * r01x);

    if (l < NQ) out[e * NQ + l] = ev;
}

extern "C" void kernel_launch(void* const* d_in, const int* in_sizes, int n_in,
                              void* d_out, int out_size)
{
    const float* x = (const float*)d_in[0];   // (B, 13) float32
    const float* w = (const float*)d_in[1];   // (2, 13, 3) float32
    float* out     = (float*)d_out;           // (B, 13) float32

    const int B = in_sizes[0] / NQ;           // 512
    const int blocks = (B + 7) / 8;           // 64 CTAs x 256 threads
    qsim_tn<<<blocks, 256>>>(x, w, out, B);
}

// round 15
// speedup vs baseline: 1.0337x; 1.0337x over previous
#include <cuda_runtime.h>

#define NQ 13
#define FULL 0xffffffffu

// One transfer step (verified R5-R14): v_new = L(v) given wire params.
__device__ __forceinline__ void tstep(
    float i00, float i11, float i01x, float i01y,
    float g0x, float g0y, float g1x, float g1y,
    float gm, float gux, float guy,
    float& o00, float& o11, float& o01x, float& o01y)
{
    const float h00x = fmaf(g0x, i00, fmaf(g1x, i01x, -g1y * i01y));
    const float h00y = fmaf(g0y, i00, fmaf(g1x, i01y,  g1y * i01x));
    const float h01x = fmaf(g1x, i00, fmaf(g0x, i01x, -g0y * i01y));
    const float h01y = fmaf(g1y, i00, fmaf(g0x, i01y,  g0y * i01x));
    const float h10x = fmaf(g1x, i11, fmaf(g0x, i01x,  g0y * i01y));
    const float h10y = fmaf(g1y, i11, fmaf(g0y, i01x, -g0x * i01y));
    const float h11x = fmaf(g0x, i11, fmaf(g1x, i01x,  g1y * i01y));
    const float h11y = fmaf(g0y, i11, fmaf(g1y, i01x, -g1x * i01y));
    const float w00  = fmaf(g0x, h00x, g0y * h00y) + fmaf(g1x, h10x, g1y * h10y);
    const float w01x = fmaf(g0x, h01x, g0y * h01y) + fmaf(g1x, h11x, g1y * h11y);
    const float w01y = fmaf(g0x, h01y, -g0y * h01x) + fmaf(g1x, h11y, -g1y * h11x);
    const float w11  = fmaf(g1x, h01x, g1y * h01y) + fmaf(g0x, h11x, g0y * h11y);
    o00  =  gm * w00;
    o11  = -gm * w11;
    o01x = fmaf(gux, w01x, -guy * w01y);
    o01y = fmaf(gux, w01y,  guy * w01x);
}

// Transfer-matrix contraction with LOG-DEPTH prefix scan + split trig.
// One warp per element, 8 warps/CTA (measured-best grid: 64 CTAs x 256).
//   - lanes 0..12:  layer-1 phi + kappa for wire l   (3 sincosf)
//   - lanes 16..28: layer-2 (m,mu) for wire l-16     (2 sincosf, concurrent)
//   - lane l builds its 4x4 transfer matrix L_l (M params via 3 shuffles)
//   - Kogge-Stone scan (4 rounds) -> lane l holds P_l = L_l ... L_1
//   - ev[l] = (1,1,2*kappa_{l+1},0) . (P_l . v0);  one coalesced store.
__global__ __launch_bounds__(256, 1)
void qsim_tn(const float* __restrict__ x,
             const float* __restrict__ wts,
             float* __restrict__ out,
             int n)
{
    const int e = blockIdx.x * 8 + (threadIdx.x >> 5);
    const int l = threadIdx.x & 31;
    if (e >= n) return;

    // ---- split per-lane parameter computation ----
    float p0x = 1.f, p0y = 0.f, p1x = 0.f, p1y = 0.f, kap = 0.f;
    float m2 = 1.f, mux2 = 0.f, muy2 = 0.f;   // layer-2 params, lanes 16..28

    if (l < NQ) {
        // layer-1 wire l: phi = first column of RZ*RY*RX (half angles)
        const float xv  = __ldg(&x[e * NQ + l]);
        const float wa0 = __ldg(&wts[l * 3 + 0]);
        const float wa1 = __ldg(&wts[l * 3 + 1]);
        const float wa2 = __ldg(&wts[l * 3 + 2]);
        float s1, c1, s2, c2, sp, cp;
        __sincosf(0.5f * xv * wa0, &s1, &c1);
        __sincosf(0.5f * xv * wa1, &s2, &c2);
        __sincosf(0.5f * wa2,      &sp, &cp);
        const float A = c2 * c1, B = s2 * s1, C = s2 * c1, D = c2 * s1;
        p0x = fmaf(cp, A,  sp * B);
        p0y = fmaf(cp, B, -sp * A);
        p1x = fmaf(cp, C,  sp * D);
        p1y = fmaf(sp, C, -cp * D);
        kap = 2.f * fmaf(p0x, p1x, p0y * p1y);
    } else if (l >= 16 && l < 16 + NQ) {
        // layer-2 wire l-16: M = U+ Z U, RZ cancels (full angles)
        const int q = l - 16;
        const float xv  = __ldg(&x[e * NQ + q]);
        const float wb0 = __ldg(&wts[(NQ + q) * 3 + 0]);
        const float wb1 = __ldg(&wts[(NQ + q) * 3 + 1]);
        float sa, ca, sb, cb;
        __sincosf(xv * wb0, &sa, &ca);
        __sincosf(xv * wb1, &sb, &cb);
        m2   = ca * cb;
        mux2 = -sb;
        muy2 = -sa * cb;
    }

    // fetch wire-l layer-2 params from lane 16+l
    const int msrc = 16 + (l & 15);
    const float m   = __shfl_sync(FULL, m2,   msrc);
    const float mux = __shfl_sync(FULL, mux2, msrc);
    const float muy = __shfl_sync(FULL, muy2, msrc);

    // ---- build 4x4 transfer matrix L (P[r*4+c]); lane 0 & lanes>=13: I ----
    float P[16];
    if (l >= 1 && l < NQ) {
        tstep(1.f, 0.f, 0.f, 0.f, p0x, p0y, p1x, p1y, m, mux, muy,
              P[0], P[4], P[8],  P[12]);
        tstep(0.f, 1.f, 0.f, 0.f, p0x, p0y, p1x, p1y, m, mux, muy,
              P[1], P[5], P[9],  P[13]);
        tstep(0.f, 0.f, 1.f, 0.f, p0x, p0y, p1x, p1y, m, mux, muy,
              P[2], P[6], P[10], P[14]);
        tstep(0.f, 0.f, 0.f, 1.f, p0x, p0y, p1x, p1y, m, mux, muy,
              P[3], P[7], P[11], P[15]);
    } else {
        #pragma unroll
        for (int i = 0; i < 16; i++) P[i] = 0.f;
        P[0] = P[5] = P[10] = P[15] = 1.f;
    }

    // ---- Kogge-Stone inclusive scan: P_l <- P_l x P_{l-d} ----
    #pragma unroll
    for (int d = 1; d < 16; d <<= 1) {
        float O[16];
        #pragma unroll
        for (int i = 0; i < 16; i++) O[i] = __shfl_up_sync(FULL, P[i], d);
        if (l >= d) {
            float T[16];
            #pragma unroll
            for (int r = 0; r < 4; r++)
                #pragma unroll
                for (int c = 0; c < 4; c++)
                    T[r * 4 + c] = fmaf(P[r * 4 + 0], O[0 * 4 + c],
                                   fmaf(P[r * 4 + 1], O[1 * 4 + c],
                                   fmaf(P[r * 4 + 2], O[2 * 4 + c],
                                        P[r * 4 + 3] * O[3 * 4 + c])));
            #pragma unroll
            for (int i = 0; i < 16; i++) P[i] = T[i];
        }
    }

    // ---- v0 from wire-0 params (phi from lane 0, M from lane 16) ----
    const float q0x = __shfl_sync(FULL, p0x, 0);
    const float q0y = __shfl_sync(FULL, p0y, 0);
    const float q1x = __shfl_sync(FULL, p1x, 0);
    const float q1y = __shfl_sync(FULL, p1y, 0);
    const float qm  = __shfl_sync(FULL, m2,   16);
    const float qux = __shfl_sync(FULL, mux2, 16);
    const float quy = __shfl_sync(FULL, muy2, 16);
    const float v000  =  qm * fmaf(q0x, q0x, q0y * q0y);
    const float v011  = -qm * fmaf(q1x, q1x, q1y * q1y);
    const float tx    = fmaf(q0x, q1x,  q0y * q1y);
    const float ty    = fmaf(q0x, q1y, -q0y * q1x);
    const float v001x = fmaf(qux, tx, -quy * ty);
    const float v001y = fmaf(qux, ty,  quy * tx);

    // ---- v_l = P_l . v0 (rows 0,1,2 only needed) ----
    const float r00  = fmaf(P[0],  v000, fmaf(P[1],  v011, fmaf(P[2],  v001x, P[3]  * v001y)));
    const float r11  = fmaf(P[4],  v000, fmaf(P[5],  v011, fmaf(P[6],  v001x, P[7]  * v001y)));
    const float r01x = fmaf(P[8],  v000, fmaf(P[9],  v011, fmaf(P[10], v001x, P[11] * v001y)));

    // ---- ev[l] = v00+v11 + kappa_{l+1} * 2*v01x  (lane 12: kappa=1) ----
    const float knext = __shfl_sync(FULL, kap, (l + 1) & 31);
    const float gk = (l == NQ - 1) ? 1.f : knext;
    const float ev = r00 + r11 + gk * (2.f * r01x);

    if (l < NQ) out[e * NQ + l] = ev;
}

extern "C" void kernel_launch(void* const* d_in, const int* in_sizes, int n_in,
                              void* d_out, int out_size)
{
    const float* x = (const float*)d_in[0];   // (B, 13) float32
    const float* w = (const float*)d_in[1];   // (2, 13, 3) float32
    float* out     = (float*)d_out;           // (B, 13) float32

    const int B = in_sizes[0] / NQ;           // 512
    const int blocks = (B + 7) / 8;           // 64 CTAs x 256 threads
    qsim_tn<<<blocks, 256>>>(x, w, out, B);
}